// round 3
// baseline (speedup 1.0000x reference)
#include <cuda_runtime.h>
#include <math.h>
#include <stdint.h>

#define K_COMP 8192
#define N_SAMP 8192
#define B_X    2048
#define D_W    13

#define LOG_2PI 1.8378770664093453f
#define L2E     1.4426950408889634f

#define MT 64            // M rows per block tile
#define NT 128           // N cols per block tile
#define MTILES (N_SAMP / MT)   // 128
#define NTILES (K_COMP / NT)   // 64

// ---------------- scratch (no allocations allowed) ----------------
__device__ float g_empT[D_W][K_COMP];   // emp transposed [d][k]
__device__ float g_wT[D_W][N_SAMP];     // w transposed  [d][s]
__device__ float g_std[K_COMP];
__device__ float g_u[K_COMP];           // L2E*(c_k - 0.5*inv_var*en_k)
__device__ float g_g[K_COMP];           // L2E*inv_var
__device__ float g_wn[N_SAMP];          // ||w_s||^2
__device__ float g_dsum[N_SAMP];        // sum_b (y_pred - y)^2
__device__ float g_SP[NTILES][N_SAMP];  // per-(ntile,row) partial exp-sums

typedef unsigned long long ull;

__device__ __forceinline__ float tanh_fast(float x) {
    float r; asm("tanh.approx.f32 %0, %1;" : "=f"(r) : "f"(x)); return r;
}
__device__ __forceinline__ float exp2_fast(float x) {
    float r; asm("ex2.approx.f32 %0, %1;" : "=f"(r) : "f"(x)); return r;
}
__device__ __forceinline__ ull pack2(float lo, float hi) {
    ull r; asm("mov.b64 %0, {%1, %2};" : "=l"(r) : "f"(lo), "f"(hi)); return r;
}
__device__ __forceinline__ void unpack2(ull v, float& lo, float& hi) {
    asm("mov.b64 {%0, %1}, %2;" : "=f"(lo), "=f"(hi) : "l"(v));
}
__device__ __forceinline__ ull fma2(ull a, ull b, ull c) {
    ull d; asm("fma.rn.f32x2 %0, %1, %2, %3;" : "=l"(d) : "l"(a), "l"(b), "l"(c)); return d;
}

// ---------------- kernel 1: per-component precompute ----------------
__global__ void prep_k(const float* __restrict__ emp, const float* __restrict__ rhos) {
    int k = blockIdx.x * blockDim.x + threadIdx.x;
    if (k >= K_COMP) return;
    float rho = rhos[k];
    float sd = (rho > 20.f) ? rho : log1pf(__expf(rho));   // softplus
    float var = sd * sd;
    float inv = 1.f / var;
    float en = 0.f;
#pragma unroll
    for (int d = 0; d < D_W; d++) {
        float v = __ldg(&emp[k * D_W + d]);
        g_empT[d][k] = v;
        en = fmaf(v, v, en);
    }
    float c = -0.5f * ((float)D_W * LOG_2PI + (float)D_W * logf(var));
    g_std[k] = sd;
    g_u[k]   = L2E * (c - 0.5f * inv * en);
    g_g[k]   = L2E * inv;
}

// ---------------- kernel 2: per-sample w, norms ----------------
__global__ void prep_s(const float* __restrict__ emp, const float* __restrict__ eps,
                       const int* __restrict__ idxs) {
    int s = blockIdx.x * blockDim.x + threadIdx.x;
    if (s >= N_SAMP) return;
    int idx = idxs[s];
    float sd = g_std[idx];
    float wn = 0.f;
#pragma unroll
    for (int d = 0; d < D_W; d++) {
        float e = __ldg(&eps[s * D_W + d]);
        float w = fmaf(e, sd, __ldg(&emp[idx * D_W + d]));
        g_wT[d][s] = w;
        wn = fmaf(w, w, wn);
    }
    g_wn[s] = wn;
}

// ---------------- kernel 3: regression data term ----------------
__global__ __launch_bounds__(1024) void reg_kernel(const float* __restrict__ x,
                                                   const float* __restrict__ y) {
    __shared__ float sx[B_X];
    __shared__ float sy[B_X];
    for (int i = threadIdx.x; i < B_X; i += blockDim.x) { sx[i] = x[i]; sy[i] = y[i]; }
    __syncthreads();

    int warp = threadIdx.x >> 5, lane = threadIdx.x & 31;
    int s = blockIdx.x * (blockDim.x >> 5) + warp;

    float p[D_W];
#pragma unroll
    for (int d = 0; d < D_W; d++) p[d] = g_wT[d][s];
    float w10 = p[0], w11 = p[1], b10 = p[2], b11 = p[3];
    float w200 = p[4], w201 = p[5], w210 = p[6], w211 = p[7];
    float b20 = p[8], b21 = p[9], w30 = p[10], w31 = p[11], b3 = p[12];

    float acc = 0.f;
#pragma unroll 4
    for (int t = 0; t < B_X / 32; t++) {
        int pix = t * 32 + lane;
        float xv = sx[pix], yv = sy[pix];
        float h0 = tanh_fast(fmaf(w10, xv, b10));
        float h1 = tanh_fast(fmaf(w11, xv, b11));
        float z0 = tanh_fast(fmaf(w200, h0, fmaf(w201, h1, b20)));
        float z1 = tanh_fast(fmaf(w210, h0, fmaf(w211, h1, b21)));
        float yp = fmaf(w30, z0, fmaf(w31, z1, b3));
        float d = yp - yv;
        acc = fmaf(d, d, acc);
    }
#pragma unroll
    for (int o = 16; o; o >>= 1) acc += __shfl_xor_sync(0xffffffffu, acc, o);
    if (lane == 0) g_dsum[s] = acc;
}

// ---------------- kernel 4: GEMM + unshifted exp-sum ----------------
// one (mtile, ntile) per block; 256 threads = 16(ty, 4 rows) x 16(tx, 8 cols)
// per-thread 4M x 8N register tile, f32x2 packed FMAs.
__global__ __launch_bounds__(256, 4) void lse_kernel() {
    __shared__ float sw[D_W][MT];     // w tile  [k][row]
    __shared__ float se[D_W][NT];     // emp tile[k][col]
    __shared__ float su[NT];
    __shared__ float sg[NT];

    int tid = threadIdx.x;
    int tx = tid & 15;        // N direction, 8 cols each
    int ty = tid >> 4;        // M direction, 4 rows each
    int m0 = blockIdx.x * MT;
    int n0 = blockIdx.y * NT;

    for (int i = tid; i < D_W * MT; i += 256) {
        int d = i / MT, c = i % MT;
        sw[d][c] = g_wT[d][m0 + c];
    }
    for (int i = tid; i < D_W * NT; i += 256) {
        int d = i / NT, c = i % NT;
        se[d][c] = g_empT[d][n0 + c];
    }
    if (tid < NT) { su[tid] = g_u[n0 + tid]; sg[tid] = g_g[n0 + tid]; }

    // acc init: A = dot - 0.5||w||^2  (seed with -0.5*wn, broadcast to both halves)
    ull acc2[4][4];
    {
        int row = m0 + ty * 4;
        float w0 = -0.5f * g_wn[row + 0];
        float w1 = -0.5f * g_wn[row + 1];
        float w2 = -0.5f * g_wn[row + 2];
        float w3 = -0.5f * g_wn[row + 3];
        ull i0 = pack2(w0, w0), i1 = pack2(w1, w1), i2 = pack2(w2, w2), i3 = pack2(w3, w3);
#pragma unroll
        for (int cc = 0; cc < 4; cc++) {
            acc2[0][cc] = i0; acc2[1][cc] = i1; acc2[2][cc] = i2; acc2[3][cc] = i3;
        }
    }
    __syncthreads();

#pragma unroll
    for (int k = 0; k < D_W; k++) {
        float4 wv = *(const float4*)&sw[k][ty * 4];
        float4 e0 = *(const float4*)&se[k][tx * 8];
        float4 e1 = *(const float4*)&se[k][tx * 8 + 4];
        ull wr[4] = { pack2(wv.x, wv.x), pack2(wv.y, wv.y),
                      pack2(wv.z, wv.z), pack2(wv.w, wv.w) };
        ull ec[4] = { pack2(e0.x, e0.y), pack2(e0.z, e0.w),
                      pack2(e1.x, e1.y), pack2(e1.z, e1.w) };
#pragma unroll
        for (int r = 0; r < 4; r++)
#pragma unroll
            for (int cc = 0; cc < 4; cc++)
                acc2[r][cc] = fma2(wr[r], ec[cc], acc2[r][cc]);
    }

    // epilogue: t = g_k * A + u_k  (base-2, UNSHIFTED: t <= L2E*c_k < 0, no overflow;
    //           own-component term bounds S below ~2^-60, no fatal underflow)
    float S[4] = {0.f, 0.f, 0.f, 0.f};
    {
        float4 gq0 = *(const float4*)&sg[tx * 8];
        float4 gq1 = *(const float4*)&sg[tx * 8 + 4];
        float4 uq0 = *(const float4*)&su[tx * 8];
        float4 uq1 = *(const float4*)&su[tx * 8 + 4];
        ull g2[4] = { pack2(gq0.x, gq0.y), pack2(gq0.z, gq0.w),
                      pack2(gq1.x, gq1.y), pack2(gq1.z, gq1.w) };
        ull u2[4] = { pack2(uq0.x, uq0.y), pack2(uq0.z, uq0.w),
                      pack2(uq1.x, uq1.y), pack2(uq1.z, uq1.w) };
#pragma unroll
        for (int cc = 0; cc < 4; cc++) {
#pragma unroll
            for (int r = 0; r < 4; r++) {
                ull t2 = fma2(g2[cc], acc2[r][cc], u2[cc]);
                float t0, t1;
                unpack2(t2, t0, t1);
                S[r] += exp2_fast(t0);
                S[r] += exp2_fast(t1);
            }
        }
    }

    // reduce across the 16 tx lanes (xor over lane bits 0-3 stays within each half-warp)
#pragma unroll
    for (int r = 0; r < 4; r++) {
        float v = S[r];
#pragma unroll
        for (int o = 8; o; o >>= 1) v += __shfl_xor_sync(0xffffffffu, v, o);
        if (tx == 0) g_SP[blockIdx.y][m0 + ty * 4 + r] = v;
    }
}

// ---------------- kernel 5: final deterministic reduction ----------------
__global__ __launch_bounds__(1024) void final_kernel(float* __restrict__ out) {
    __shared__ double sh[3][32];
    int tid = threadIdx.x;
    double qs = 0.0, wns = 0.0, ds = 0.0;
    for (int s = tid; s < N_SAMP; s += 1024) {
        float S = 0.f;
#pragma unroll
        for (int c = 0; c < NTILES; c++) S += g_SP[c][s];
        qs  += (double)logf(S);
        wns += (double)g_wn[s];
        ds  += (double)g_dsum[s];
    }
    int lane = tid & 31, warp = tid >> 5;
#pragma unroll
    for (int o = 16; o; o >>= 1) {
        qs  += __shfl_xor_sync(0xffffffffu, qs, o);
        wns += __shfl_xor_sync(0xffffffffu, wns, o);
        ds  += __shfl_xor_sync(0xffffffffu, ds, o);
    }
    if (lane == 0) { sh[0][warp] = qs; sh[1][warp] = wns; sh[2][warp] = ds; }
    __syncthreads();
    if (warp == 0) {
        qs = sh[0][lane]; wns = sh[1][lane]; ds = sh[2][lane];
#pragma unroll
        for (int o = 16; o; o >>= 1) {
            qs  += __shfl_xor_sync(0xffffffffu, qs, o);
            wns += __shfl_xor_sync(0xffffffffu, wns, o);
            ds  += __shfl_xor_sync(0xffffffffu, ds, o);
        }
        if (lane == 0) {
            const double LOG_2PI_D = 1.837877066409345483560659472811;
            double mean_q  = qs / (double)N_SAMP - log((double)K_COMP);
            double mean_wn = wns / (double)N_SAMP;
            double mean_d  = ds / (double)N_SAMP;
            double data_lp = -0.5 * 5.0 * mean_d
                           + (double)B_X * 0.5 * (log(5.0) - LOG_2PI_D);
            double prior   = -0.5 * mean_wn - 0.5 * (double)D_W * LOG_2PI_D;
            double kl      = mean_q - prior;
            out[0] = (float)(data_lp - kl);
        }
    }
}

// ---------------- launch ----------------
extern "C" void kernel_launch(void* const* d_in, const int* in_sizes, int n_in,
                              void* d_out, int out_size) {
    const float* emp  = (const float*)d_in[0];
    const float* rhos = (const float*)d_in[1];
    const float* x    = (const float*)d_in[2];
    const float* y    = (const float*)d_in[3];
    const float* eps  = (const float*)d_in[4];
    const int*   idxs = (const int*)d_in[5];
    float* out = (float*)d_out;

    prep_k<<<(K_COMP + 255) / 256, 256>>>(emp, rhos);
    prep_s<<<(N_SAMP + 255) / 256, 256>>>(emp, eps, idxs);
    reg_kernel<<<N_SAMP / 32, 1024>>>(x, y);
    lse_kernel<<<dim3(MTILES, NTILES), 256>>>();
    final_kernel<<<1, 1024>>>(out);
}

// round 4
// speedup vs baseline: 1.0753x; 1.0753x over previous
#include <cuda_runtime.h>
#include <math.h>
#include <stdint.h>

#define K_COMP 8192
#define N_SAMP 8192
#define B_X    2048
#define D_W    13

#define LOG_2PI 1.8378770664093453f
#define L2E     1.4426950408889634f

#define MT 64                      // M rows per block tile
#define NT 128                     // N cols per tile
#define NCHUNK 16                  // n-chunks (blockIdx.y)
#define TPC (K_COMP / NT / NCHUNK) // 4 n-tiles per block
#define MTILES (N_SAMP / MT)       // 128

typedef unsigned long long ull;

// ---------------- scratch (no allocations allowed) ----------------
__device__ float g_empT[D_W][K_COMP];   // emp transposed [d][k]
__device__ float g_wT[D_W][N_SAMP];     // w transposed  [d][s]
__device__ float g_std[K_COMP];
__device__ float g_u[K_COMP];           // L2E*(c_k - 0.5*inv_var*en_k)
__device__ float g_g[K_COMP];           // L2E*inv_var
__device__ float g_wn[N_SAMP];          // ||w_s||^2
__device__ float g_dsum[N_SAMP];        // sum_b (y_pred - y)^2
__device__ float g_SP[NCHUNK][N_SAMP];  // per-chunk partial exp-sums
__device__ float g_q[N_SAMP];           // log(sum)

__device__ __forceinline__ float tanh_fast(float x) {
    float r; asm("tanh.approx.f32 %0, %1;" : "=f"(r) : "f"(x)); return r;
}
__device__ __forceinline__ float exp2_fast(float x) {
    float r; asm("ex2.approx.f32 %0, %1;" : "=f"(r) : "f"(x)); return r;
}
__device__ __forceinline__ ull pack2(float lo, float hi) {
    ull r; asm("mov.b64 %0, {%1, %2};" : "=l"(r) : "f"(lo), "f"(hi)); return r;
}
__device__ __forceinline__ void unpack2(ull v, float& lo, float& hi) {
    asm("mov.b64 {%0, %1}, %2;" : "=f"(lo), "=f"(hi) : "l"(v));
}
__device__ __forceinline__ ull fma2(ull a, ull b, ull c) {
    ull d; asm("fma.rn.f32x2 %0, %1, %2, %3;" : "=l"(d) : "l"(a), "l"(b), "l"(c)); return d;
}

// ---------------- kernel 1: per-component precompute ----------------
__global__ void prep_k(const float* __restrict__ emp, const float* __restrict__ rhos) {
    int k = blockIdx.x * blockDim.x + threadIdx.x;
    if (k >= K_COMP) return;
    float rho = rhos[k];
    float sd = (rho > 20.f) ? rho : log1pf(__expf(rho));   // softplus
    float var = sd * sd;
    float inv = 1.f / var;
    float en = 0.f;
#pragma unroll
    for (int d = 0; d < D_W; d++) {
        float v = __ldg(&emp[k * D_W + d]);
        g_empT[d][k] = v;
        en = fmaf(v, v, en);
    }
    float c = -0.5f * ((float)D_W * LOG_2PI + (float)D_W * logf(var));
    g_std[k] = sd;
    g_u[k]   = L2E * (c - 0.5f * inv * en);
    g_g[k]   = L2E * inv;
}

// ---------------- kernel 2: per-sample w, norms ----------------
__global__ void prep_s(const float* __restrict__ emp, const float* __restrict__ eps,
                       const int* __restrict__ idxs) {
    int s = blockIdx.x * blockDim.x + threadIdx.x;
    if (s >= N_SAMP) return;
    int idx = idxs[s];
    float sd = g_std[idx];
    float wn = 0.f;
#pragma unroll
    for (int d = 0; d < D_W; d++) {
        float e = __ldg(&eps[s * D_W + d]);
        float w = fmaf(e, sd, __ldg(&emp[idx * D_W + d]));
        g_wT[d][s] = w;
        wn = fmaf(w, w, wn);
    }
    g_wn[s] = wn;
}

// ---------------- kernel 3: regression data term ----------------
__global__ __launch_bounds__(1024) void reg_kernel(const float* __restrict__ x,
                                                   const float* __restrict__ y) {
    __shared__ float sx[B_X];
    __shared__ float sy[B_X];
    for (int i = threadIdx.x; i < B_X; i += blockDim.x) { sx[i] = x[i]; sy[i] = y[i]; }
    __syncthreads();

    int warp = threadIdx.x >> 5, lane = threadIdx.x & 31;
    int s = blockIdx.x * (blockDim.x >> 5) + warp;

    float p[D_W];
#pragma unroll
    for (int d = 0; d < D_W; d++) p[d] = g_wT[d][s];
    float w10 = p[0], w11 = p[1], b10 = p[2], b11 = p[3];
    float w200 = p[4], w201 = p[5], w210 = p[6], w211 = p[7];
    float b20 = p[8], b21 = p[9], w30 = p[10], w31 = p[11], b3 = p[12];

    float acc = 0.f;
#pragma unroll 4
    for (int t = 0; t < B_X / 32; t++) {
        int pix = t * 32 + lane;
        float xv = sx[pix], yv = sy[pix];
        float h0 = tanh_fast(fmaf(w10, xv, b10));
        float h1 = tanh_fast(fmaf(w11, xv, b11));
        float z0 = tanh_fast(fmaf(w200, h0, fmaf(w201, h1, b20)));
        float z1 = tanh_fast(fmaf(w210, h0, fmaf(w211, h1, b21)));
        float yp = fmaf(w30, z0, fmaf(w31, z1, b3));
        float d = yp - yv;
        acc = fmaf(d, d, acc);
    }
#pragma unroll
    for (int o = 16; o; o >>= 1) acc += __shfl_xor_sync(0xffffffffu, acc, o);
    if (lane == 0) g_dsum[s] = acc;
}

// ---------------- kernel 4: GEMM + unshifted exp-sum ----------------
// block = 256 thr (16 tx x 16 ty); M-tile 64 rows (4/thread, duplicated-pair
// smem), 4 N-tiles of 128 cols (8/thread, natural pairs). Inner loop has
// ZERO pack instructions: both operands come out of smem already f32x2-shaped.
__global__ __launch_bounds__(256, 4) void lse_kernel() {
    __shared__ __align__(16) ull sw2[D_W][MT];      // (w,w) dup pairs  [k][row]
    __shared__ __align__(16) ull se2[D_W][NT / 2];  // (e0,e1) pairs    [k][colpair]
    __shared__ __align__(16) ull su2[NT / 2];
    __shared__ __align__(16) ull sg2[NT / 2];

    int tid = threadIdx.x;
    int tx = tid & 15;        // N direction: 4 col-pairs = 8 cols
    int ty = tid >> 4;        // M direction: 4 rows
    int m0 = blockIdx.x * MT;

    // w tile: load once, store duplicated pairs
    for (int i = tid; i < D_W * MT; i += 256) {
        int d = i >> 6, r = i & 63;
        float v = g_wT[d][m0 + r];
        sw2[d][r] = pack2(v, v);
    }
    float wnh[4], S[4];
#pragma unroll
    for (int r = 0; r < 4; r++) {
        wnh[r] = -0.5f * g_wn[m0 + ty * 4 + r];
        S[r] = 0.f;
    }

#pragma unroll 1
    for (int t = 0; t < TPC; t++) {
        int n0 = (blockIdx.y * TPC + t) * NT;
        __syncthreads();
        for (int i = tid; i < D_W * (NT / 2); i += 256) {
            int d = i >> 6, c = i & 63;
            float2 e = *(const float2*)&g_empT[d][n0 + 2 * c];
            se2[d][c] = pack2(e.x, e.y);
        }
        if (tid < NT / 2) {
            float2 u = *(const float2*)&g_u[n0 + 2 * tid];
            float2 g = *(const float2*)&g_g[n0 + 2 * tid];
            su2[tid] = pack2(u.x, u.y);
            sg2[tid] = pack2(g.x, g.y);
        }
        __syncthreads();

        ull acc[4][4];   // [row][colpair], init A = -0.5||w||^2
#pragma unroll
        for (int r = 0; r < 4; r++) {
            ull iv = pack2(wnh[r], wnh[r]);
#pragma unroll
            for (int c = 0; c < 4; c++) acc[r][c] = iv;
        }

#pragma unroll
        for (int k = 0; k < D_W; k++) {
            ulonglong2 wa = *(const ulonglong2*)&sw2[k][ty * 4];
            ulonglong2 wb = *(const ulonglong2*)&sw2[k][ty * 4 + 2];
            ulonglong2 ea = *(const ulonglong2*)&se2[k][tx * 4];
            ulonglong2 eb = *(const ulonglong2*)&se2[k][tx * 4 + 2];
            ull wr[4] = { wa.x, wa.y, wb.x, wb.y };
            ull ec[4] = { ea.x, ea.y, eb.x, eb.y };
#pragma unroll
            for (int r = 0; r < 4; r++)
#pragma unroll
                for (int c = 0; c < 4; c++)
                    acc[r][c] = fma2(wr[r], ec[c], acc[r][c]);
        }

        // epilogue: t = g_k*A + u_k (base-2, unshifted: t <= L2E*c_k < 0 so no
        // overflow; own-component term keeps S >= ~2^-25, no fatal underflow)
        {
            ulonglong2 ga = *(const ulonglong2*)&sg2[tx * 4];
            ulonglong2 gb = *(const ulonglong2*)&sg2[tx * 4 + 2];
            ulonglong2 ua = *(const ulonglong2*)&su2[tx * 4];
            ulonglong2 ub = *(const ulonglong2*)&su2[tx * 4 + 2];
            ull g2[4] = { ga.x, ga.y, gb.x, gb.y };
            ull u2[4] = { ua.x, ua.y, ub.x, ub.y };
#pragma unroll
            for (int c = 0; c < 4; c++) {
#pragma unroll
                for (int r = 0; r < 4; r++) {
                    ull t2 = fma2(g2[c], acc[r][c], u2[c]);
                    float t0, t1;
                    unpack2(t2, t0, t1);
                    S[r] += exp2_fast(t0) + exp2_fast(t1);
                }
            }
        }
    }

    // reduce across the 16 tx lanes (xor over lane bits 0-3)
#pragma unroll
    for (int r = 0; r < 4; r++) {
        float v = S[r];
#pragma unroll
        for (int o = 8; o; o >>= 1) v += __shfl_xor_sync(0xffffffffu, v, o);
        if (tx == 0) g_SP[blockIdx.y][m0 + ty * 4 + r] = v;
    }
}

// ---------------- kernel 5: parallel per-sample reduction + log ----------------
__global__ void reduce_sp() {
    int s = blockIdx.x * blockDim.x + threadIdx.x;
    if (s >= N_SAMP) return;
    float S = 0.f;
#pragma unroll
    for (int c = 0; c < NCHUNK; c++) S += g_SP[c][s];
    g_q[s] = logf(S);
}

// ---------------- kernel 6: final deterministic reduction ----------------
__global__ __launch_bounds__(1024) void final_kernel(float* __restrict__ out) {
    __shared__ double sh[3][32];
    int tid = threadIdx.x;
    double qs = 0.0, wns = 0.0, ds = 0.0;
    for (int s = tid; s < N_SAMP; s += 1024) {
        qs  += (double)g_q[s];
        wns += (double)g_wn[s];
        ds  += (double)g_dsum[s];
    }
    int lane = tid & 31, warp = tid >> 5;
#pragma unroll
    for (int o = 16; o; o >>= 1) {
        qs  += __shfl_xor_sync(0xffffffffu, qs, o);
        wns += __shfl_xor_sync(0xffffffffu, wns, o);
        ds  += __shfl_xor_sync(0xffffffffu, ds, o);
    }
    if (lane == 0) { sh[0][warp] = qs; sh[1][warp] = wns; sh[2][warp] = ds; }
    __syncthreads();
    if (warp == 0) {
        qs = sh[0][lane]; wns = sh[1][lane]; ds = sh[2][lane];
#pragma unroll
        for (int o = 16; o; o >>= 1) {
            qs  += __shfl_xor_sync(0xffffffffu, qs, o);
            wns += __shfl_xor_sync(0xffffffffu, wns, o);
            ds  += __shfl_xor_sync(0xffffffffu, ds, o);
        }
        if (lane == 0) {
            const double LOG_2PI_D = 1.837877066409345483560659472811;
            double mean_q  = qs / (double)N_SAMP - log((double)K_COMP);
            double mean_wn = wns / (double)N_SAMP;
            double mean_d  = ds / (double)N_SAMP;
            double data_lp = -0.5 * 5.0 * mean_d
                           + (double)B_X * 0.5 * (log(5.0) - LOG_2PI_D);
            double prior   = -0.5 * mean_wn - 0.5 * (double)D_W * LOG_2PI_D;
            double kl      = mean_q - prior;
            out[0] = (float)(data_lp - kl);
        }
    }
}

// ---------------- launch ----------------
extern "C" void kernel_launch(void* const* d_in, const int* in_sizes, int n_in,
                              void* d_out, int out_size) {
    const float* emp  = (const float*)d_in[0];
    const float* rhos = (const float*)d_in[1];
    const float* x    = (const float*)d_in[2];
    const float* y    = (const float*)d_in[3];
    const float* eps  = (const float*)d_in[4];
    const int*   idxs = (const int*)d_in[5];
    float* out = (float*)d_out;

    prep_k<<<(K_COMP + 255) / 256, 256>>>(emp, rhos);
    prep_s<<<(N_SAMP + 255) / 256, 256>>>(emp, eps, idxs);
    reg_kernel<<<N_SAMP / 32, 1024>>>(x, y);
    lse_kernel<<<dim3(MTILES, NCHUNK), 256>>>();
    reduce_sp<<<N_SAMP / 256, 256>>>();
    final_kernel<<<1, 1024>>>(out);
}